// round 1
// baseline (speedup 1.0000x reference)
#include <cuda_runtime.h>
#include <cuda_bf16.h>

#define N_NODES 50000
#define NPAD    50016
#define D_EMB   64
#define N_BATCH 64
#define POOL_BLOCKS 128

// ---------------- scratch (device globals; no allocation) ----------------
__device__ float g_hA[NPAD * D_EMB];
__device__ float g_hB[NPAD * D_EMB];
__device__ float g_hnv[NPAD * D_EMB];
__device__ float g_hsA[N_BATCH * D_EMB];
__device__ float g_hsB[N_BATCH * D_EMB];
__device__ float g_hnvs[N_BATCH * D_EMB];
__device__ float g_Wa[D_EMB * D_EMB];
__device__ float g_Wb[D_EMB * D_EMB];
__device__ int   g_rowptr[N_NODES + 1];
__device__ float g_poolpart[POOL_BLOCKS * N_BATCH * D_EMB];

// ---------------- packed f32x2 FMA (sm_103a; 2x FFMA throughput) ----------
union F2U { float2 f; unsigned long long u; };
__device__ __forceinline__ void ffma2(float2& c, float2 a, float2 b) {
    F2U A, B, C; A.f = a; B.f = b; C.f = c;
    asm("fma.rn.f32x2 %0, %1, %2, %0;" : "+l"(C.u) : "l"(A.u), "l"(B.u));
    c = C.f;
}

// ---------------- fold W2/W3 into Wl --------------------------------------
__global__ void fuse_w(const float* __restrict__ W2, const float* __restrict__ W3,
                       const float* __restrict__ Wl, float* __restrict__ Wa,
                       float* __restrict__ Wb) {
    int i = blockIdx.x;   // 64
    int j = threadIdx.x;  // 64
    float sa = 0.f, sb = 0.f;
    #pragma unroll 8
    for (int k = 0; k < 64; k++) {
        sa = fmaf(W2[i * 64 + k], Wl[k * 64 + j], sa);
        sb = fmaf(W3[i * 64 + k], Wl[(64 + k) * 64 + j], sb);
    }
    Wa[i * 64 + j] = sa;
    Wb[i * 64 + j] = sb;
}

// ---------------- build row_ptr from sorted edge_row (no scan) ------------
__global__ void build_rowptr(const int* __restrict__ row, int* __restrict__ rp,
                             int nE, int nN) {
    int e = blockIdx.x * blockDim.x + threadIdx.x;
    if (e >= nE) return;
    int r = row[e];
    int rprev = (e == 0) ? -1 : row[e - 1];
    for (int rr = rprev + 1; rr <= r; rr++) rp[rr] = e;
    if (e == nE - 1)
        for (int rr = r + 1; rr <= nN; rr++) rp[rr] = nE;
}

// ---------------- init: h = l2norm(relu(X @ W1)) (warp per row) -----------
__global__ void init_h(const float* __restrict__ X, const float* __restrict__ W1,
                       float* __restrict__ out, int n) {
    int w = (blockIdx.x * blockDim.x + threadIdx.x) >> 5;
    if (w >= n) return;
    int l = threadIdx.x & 31;
    float x0 = X[w * 2], x1 = X[w * 2 + 1];
    // dims 2l, 2l+1 per lane; W1 row-major [2,64]
    float v0 = fmaxf(fmaf(x0, W1[2 * l],     x1 * W1[64 + 2 * l]),     0.f);
    float v1 = fmaxf(fmaf(x0, W1[2 * l + 1], x1 * W1[64 + 2 * l + 1]), 0.f);
    float s = v0 * v0 + v1 * v1;
    #pragma unroll
    for (int m = 16; m; m >>= 1) s += __shfl_xor_sync(0xffffffffu, s, m);
    float inv = 1.f / fmaxf(sqrtf(s), 1e-12f);
    ((float2*)out)[w * 32 + l] = make_float2(v0 * inv, v1 * inv);
}

// ---------------- SPMM: h_nv[i] = sum_{e: row=i} h[col[e]] ----------------
// warp per node, lane owns dims (2l,2l+1), float2 gather, 4x unrolled MLP
__global__ void spmm(const float2* __restrict__ h2, const int* __restrict__ col,
                     const int* __restrict__ rp, float2* __restrict__ out) {
    int w = (blockIdx.x * blockDim.x + threadIdx.x) >> 5;
    if (w >= N_NODES) return;
    int lane = threadIdx.x & 31;
    int s = rp[w], e = rp[w + 1];
    float ax = 0.f, ay = 0.f, bx = 0.f, by = 0.f;
    int i = s;
    for (; i + 4 <= e; i += 4) {
        int c0 = __ldg(col + i);
        int c1 = __ldg(col + i + 1);
        int c2 = __ldg(col + i + 2);
        int c3 = __ldg(col + i + 3);
        float2 v0 = h2[c0 * 32 + lane];
        float2 v1 = h2[c1 * 32 + lane];
        float2 v2 = h2[c2 * 32 + lane];
        float2 v3 = h2[c3 * 32 + lane];
        ax += v0.x + v2.x; ay += v0.y + v2.y;
        bx += v1.x + v3.x; by += v1.y + v3.y;
    }
    for (; i < e; i++) {
        int c = __ldg(col + i);
        float2 v = h2[c * 32 + lane];
        ax += v.x; ay += v.y;
    }
    out[w * 32 + lane] = make_float2(ax + bx, ay + by);
}

// ---------------- batch pooling: deterministic two-stage, no atomics ------
__global__ void __launch_bounds__(128) pool_partial(const float* __restrict__ h,
                                                    const int* __restrict__ ba, int n) {
    __shared__ float acc[2 * N_BATCH * D_EMB];  // 32 KB, 2 node-lane copies
    int t = threadIdx.x;  // 128
    for (int i = t; i < 2 * 4096; i += 128) acc[i] = 0.f;
    __syncthreads();
    int per = (n + POOL_BLOCKS - 1) / POOL_BLOCKS;
    int start = blockIdx.x * per;
    int end = min(start + per, n);
    int j = t & 63;       // dim
    int nl = t >> 6;      // node lane 0..1
    float* my = acc + nl * 4096;
    for (int nn = start + nl; nn < end; nn += 2) {
        int b = ba[nn];
        my[b * 64 + j] += h[nn * 64 + j];   // warps disjoint by (nl, j-range): no races
    }
    __syncthreads();
    for (int i = t; i < 4096; i += 128)
        g_poolpart[blockIdx.x * 4096 + i] = acc[i] + acc[4096 + i];
}

__global__ void pool_reduce(float* __restrict__ out) {
    int i = blockIdx.x * blockDim.x + threadIdx.x;  // 4096 threads
    float s = 0.f;
    #pragma unroll 8
    for (int b = 0; b < POOL_BLOCKS; b++) s += g_poolpart[b * 4096 + i];
    out[i] = s;
}

// ---------------- fused update: out = l2norm(relu(h@Wa + hnv@Wb + bl)) ----
// 128 threads / 32 nodes per block; f32x2 packed FMA; smem-staged operands
__global__ void __launch_bounds__(128) update_h(
    const float* __restrict__ h, const float* __restrict__ hnv,
    const float* __restrict__ Wa, const float* __restrict__ Wb,
    const float* __restrict__ bl, float* __restrict__ out, int nrows) {
    __shared__ float sWa[4096], sWb[4096];
    __shared__ float sh[32 * 64], shn[32 * 64];
    int t = threadIdx.x;
    for (int i = t; i < 1024; i += 128) {
        ((float4*)sWa)[i] = ((const float4*)Wa)[i];
        ((float4*)sWb)[i] = ((const float4*)Wb)[i];
    }
    int base = blockIdx.x * 32;
    const float4* h4 = (const float4*)(h + base * 64);
    const float4* hn4 = (const float4*)(hnv + base * 64);
    for (int i = t; i < 512; i += 128) {
        ((float4*)sh)[i] = h4[i];
        ((float4*)shn)[i] = hn4[i];
    }
    __syncthreads();

    int nl = t >> 2, part = t & 3;  // node-local, quarter of the 64 output dims
    float2 acc[8];
    #pragma unroll
    for (int i = 0; i < 8; i++) acc[i] = ((const float2*)bl)[part * 8 + i];

    const float4* wa4 = (const float4*)sWa;
    const float4* wb4 = (const float4*)sWb;
    const float* hr = sh + nl * 64;
    const float* hnr = shn + nl * 64;

    #pragma unroll 4
    for (int k = 0; k < 64; k++) {
        float a = hr[k], b = hnr[k];
        float2 a2 = make_float2(a, a), b2 = make_float2(b, b);
        #pragma unroll
        for (int i = 0; i < 4; i++) {
            float4 wa = wa4[k * 16 + part * 4 + i];
            ffma2(acc[2 * i],     a2, make_float2(wa.x, wa.y));
            ffma2(acc[2 * i + 1], a2, make_float2(wa.z, wa.w));
            float4 wb = wb4[k * 16 + part * 4 + i];
            ffma2(acc[2 * i],     b2, make_float2(wb.x, wb.y));
            ffma2(acc[2 * i + 1], b2, make_float2(wb.z, wb.w));
        }
    }

    // relu + row sum-of-squares (4 threads per node, consecutive lanes)
    float s = 0.f;
    #pragma unroll
    for (int i = 0; i < 8; i++) {
        acc[i].x = fmaxf(acc[i].x, 0.f);
        acc[i].y = fmaxf(acc[i].y, 0.f);
        s = fmaf(acc[i].x, acc[i].x, s);
        s = fmaf(acc[i].y, acc[i].y, s);
    }
    s += __shfl_xor_sync(0xffffffffu, s, 1);
    s += __shfl_xor_sync(0xffffffffu, s, 2);
    float inv = 1.f / fmaxf(sqrtf(s), 1e-12f);

    int n = base + nl;
    if (n < nrows) {
        float4* o4 = (float4*)(out + n * 64 + part * 16);
        #pragma unroll
        for (int i = 0; i < 4; i++)
            o4[i] = make_float4(acc[2 * i].x * inv, acc[2 * i].y * inv,
                                acc[2 * i + 1].x * inv, acc[2 * i + 1].y * inv);
    }
}

// ---------------- host orchestration --------------------------------------
extern "C" void kernel_launch(void* const* d_in, const int* in_sizes, int n_in,
                              void* d_out, int out_size) {
    const int*   edge_row     = (const int*)d_in[0];
    const int*   edge_col     = (const int*)d_in[1];
    const int*   batch_assign = (const int*)d_in[2];
    const float* X            = (const float*)d_in[3];
    const float* Xs           = (const float*)d_in[4];
    const float* W1           = (const float*)d_in[5];
    const float* W2           = (const float*)d_in[6];
    const float* W3           = (const float*)d_in[7];
    const float* Wl           = (const float*)d_in[8];
    const float* bl           = (const float*)d_in[9];
    float* out = (float*)d_out;

    int nE = in_sizes[0];

    float *hA, *hB, *hnv, *hsA, *hsB, *hnvs, *Wa, *Wb;
    int* rp;
    cudaGetSymbolAddress((void**)&hA,   g_hA);
    cudaGetSymbolAddress((void**)&hB,   g_hB);
    cudaGetSymbolAddress((void**)&hnv,  g_hnv);
    cudaGetSymbolAddress((void**)&hsA,  g_hsA);
    cudaGetSymbolAddress((void**)&hsB,  g_hsB);
    cudaGetSymbolAddress((void**)&hnvs, g_hnvs);
    cudaGetSymbolAddress((void**)&Wa,   g_Wa);
    cudaGetSymbolAddress((void**)&Wb,   g_Wb);
    cudaGetSymbolAddress((void**)&rp,   g_rowptr);

    fuse_w<<<64, 64>>>(W2, W3, Wl, Wa, Wb);
    build_rowptr<<<(nE + 255) / 256, 256>>>(edge_row, rp, nE, N_NODES);
    init_h<<<(N_NODES * 32 + 255) / 256, 256>>>(X, W1, hA, N_NODES);
    init_h<<<8, 256>>>(Xs, W1, hsA, N_BATCH);

    float* hc = hA;  float* hn_ = hB;
    float* hsc = hsA; float* hsn = hsB;
    for (int d = 0; d < 3; d++) {
        spmm<<<(N_NODES * 32 + 255) / 256, 256>>>((const float2*)hc, edge_col, rp,
                                                  (float2*)hnv);
        pool_partial<<<POOL_BLOCKS, 128>>>(hc, batch_assign, N_NODES);
        pool_reduce<<<16, 256>>>(hnvs);

        float* hout  = (d == 2) ? out : hn_;
        float* hsout = (d == 2) ? (out + N_NODES * D_EMB) : hsn;
        update_h<<<(N_NODES + 31) / 32, 128>>>(hc, hnv, Wa, Wb, bl, hout, N_NODES);
        update_h<<<2, 128>>>(hsc, hnvs, Wa, Wb, bl, hsout, N_BATCH);

        float* tmp = hc; hc = hn_; hn_ = tmp;
        tmp = hsc; hsc = hsn; hsn = tmp;
    }
}